// round 1
// baseline (speedup 1.0000x reference)
#include <cuda_runtime.h>
#include <cstdint>

// ---------------- problem constants ----------------
#define N0 400000
#define N1 120000
#define N2 20000
#define N3 4000
#define FIN 128
#define FH  256
#define FC  47

// ---------------- device scratch (static: no allocations allowed) ----------------
__device__ float g_sum0[(size_t)N1 * FIN];
__device__ float g_deg0[N1];
__device__ float g_h1[(size_t)N1 * FH];
__device__ float g_sum1[(size_t)N2 * FH];
__device__ float g_deg1[N2];
__device__ float g_h2[(size_t)N2 * FH];
__device__ float g_sum2[(size_t)N3 * FH];
__device__ float g_deg2[N3];

// ---------------- small PTX helpers ----------------
__device__ __forceinline__ void red_add4(float* p, float4 v) {
    asm volatile("red.global.add.v4.f32 [%0], {%1,%2,%3,%4};"
                 :: "l"(p), "f"(v.x), "f"(v.y), "f"(v.z), "f"(v.w) : "memory");
}
__device__ __forceinline__ void red_add1(float* p, float v) {
    asm volatile("red.global.add.f32 [%0], %1;" :: "l"(p), "f"(v) : "memory");
}
// duplicate a float into both halves of a packed f32x2
__device__ __forceinline__ unsigned long long pack2(float x) {
    unsigned long long r;
    unsigned int xi = __float_as_uint(x);
    asm("mov.b64 %0, {%1, %1};" : "=l"(r) : "r"(xi));
    return r;
}
// packed dual-FMA: d.lo += a.lo*b.lo ; d.hi += a.hi*b.hi
__device__ __forceinline__ void fma2(unsigned long long& d,
                                     unsigned long long a, unsigned long long b) {
    asm("fma.rn.f32x2 %0, %1, %2, %0;" : "+l"(d) : "l"(a), "l"(b));
}
__device__ __forceinline__ void unpack2(unsigned long long v, float& lo, float& hi) {
    unsigned int l, h;
    asm("mov.b64 {%0, %1}, %2;" : "=r"(l), "=r"(h) : "l"(v));
    lo = __uint_as_float(l); hi = __uint_as_float(h);
}

// ---------------- zero scratch ----------------
__global__ void zero_scratch() {
    size_t stride = (size_t)gridDim.x * blockDim.x;
    size_t i0 = (size_t)blockIdx.x * blockDim.x + threadIdx.x;
    float4 z = make_float4(0.f, 0.f, 0.f, 0.f);
    for (size_t i = i0; i < (size_t)N1 * FIN / 4; i += stride) ((float4*)g_sum0)[i] = z;
    for (size_t i = i0; i < (size_t)N2 * FH  / 4; i += stride) ((float4*)g_sum1)[i] = z;
    for (size_t i = i0; i < (size_t)N3 * FH  / 4; i += stride) ((float4*)g_sum2)[i] = z;
    for (size_t i = i0; i < N1 / 4; i += stride) ((float4*)g_deg0)[i] = z;
    for (size_t i = i0; i < N2 / 4; i += stride) ((float4*)g_deg1)[i] = z;
    for (size_t i = i0; i < N3 / 4; i += stride) ((float4*)g_deg2)[i] = z;
}

// ---------------- edge scatter: one warp per edge ----------------
template <int DIN>
__global__ void scatter_kernel(const float* __restrict__ h,
                               const int* __restrict__ src,
                               const int* __restrict__ dst,
                               int nE,
                               float* __restrict__ sum,
                               float* __restrict__ deg) {
    int warp = (int)((blockIdx.x * (unsigned)blockDim.x + threadIdx.x) >> 5);
    int lane = threadIdx.x & 31;
    if (warp >= nE) return;
    int s = __ldg(src + warp);
    int d = __ldg(dst + warp);
    const float4* srow = (const float4*)(h + (size_t)s * DIN);
    float* drow = sum + (size_t)d * DIN;
#pragma unroll
    for (int i = 0; i < DIN / 128; i++) {
        float4 v = __ldg(srow + lane + i * 32);
        red_add4(drow + (size_t)(lane + i * 32) * 4, v);
    }
    if (lane == 0) red_add1(deg + d, 1.0f);
}

// ---------------- fused SAGE layer: out = [self | mean] @ [Ws;Wn] + b (opt ReLU) --------
// BM=128 rows x BN=64 cols per CTA, 256 threads, full-K weight slab in smem,
// A tile staged k-major, packed f32x2 FMAs (2 output cols per accumulator).
template <int DIN, bool RELU>
__global__ void __launch_bounds__(256)
layer_kernel(const float* __restrict__ hin,   // self features [>=n, DIN]
             const float* __restrict__ nsum,  // neighbor sums [n, DIN]
             const float* __restrict__ deg,   // [n]
             const float* __restrict__ Ws,    // [DIN, dout]
             const float* __restrict__ Wn,    // [DIN, dout]
             const float* __restrict__ bias,  // [dout]
             float* __restrict__ out,         // [n, dout]
             int n, int dout) {
    constexpr int K = 2 * DIN, BM = 128, BN = 64, BK = 16;
    extern __shared__ float smem[];
    float* sW    = smem;                 // K * BN
    float* sA    = smem + K * BN;        // BK * BM  (k-major)
    float* sInvD = sA + BK * BM;         // BM

    const int tid  = threadIdx.x;
    const int rb   = blockIdx.x, cb = blockIdx.y;
    const int row0 = rb * BM;
    const int col0 = cb * BN;
    const int lane = tid & 31;
    const int cg   = tid >> 5;

    // ---- stage weight slab [K x BN] ----
    if (((dout & 3) == 0) && (col0 + BN) <= dout) {
        for (int i = tid; i < K * BN / 4; i += 256) {
            int k  = i / (BN / 4);
            int c4 = (i % (BN / 4)) * 4;
            const float* Wp = (k < DIN) ? (Ws + (size_t)k * dout)
                                        : (Wn + (size_t)(k - DIN) * dout);
            *(float4*)(sW + k * BN + c4) = *(const float4*)(Wp + col0 + c4);
        }
    } else {
        for (int i = tid; i < K * BN; i += 256) {
            int k = i / BN, c = i % BN;
            int col = col0 + c;
            float v = 0.f;
            if (col < dout)
                v = (k < DIN) ? Ws[(size_t)k * dout + col]
                              : Wn[(size_t)(k - DIN) * dout + col];
            sW[k * BN + c] = v;
        }
    }
    if (tid < BM) {
        int r = row0 + tid;
        sInvD[tid] = (r < n) ? (1.0f / fmaxf(deg[r], 1.0f)) : 0.0f;
    }
    __syncthreads();

    unsigned long long acc[4][4];
#pragma unroll
    for (int r = 0; r < 4; r++)
#pragma unroll
        for (int j = 0; j < 4; j++) acc[r][j] = 0ull;

    for (int k0 = 0; k0 < K; k0 += BK) {
        // ---- stage A chunk [BK x BM], transposed to k-major ----
#pragma unroll
        for (int it = 0; it < 2; it++) {
            int linear = tid + it * 256;           // 0..511
            int m   = linear & (BM - 1);
            int kk4 = (linear >> 7) * 4;           // 0,4,8,12
            int r = row0 + m;
            int k = k0 + kk4;
            float4 v = make_float4(0.f, 0.f, 0.f, 0.f);
            if (r < n) {
                if (k < DIN) {
                    v = *(const float4*)(hin + (size_t)r * DIN + k);
                } else {
                    v = *(const float4*)(nsum + (size_t)r * DIN + (k - DIN));
                    float sc = sInvD[m];
                    v.x *= sc; v.y *= sc; v.z *= sc; v.w *= sc;
                }
            }
            sA[(kk4 + 0) * BM + m] = v.x;
            sA[(kk4 + 1) * BM + m] = v.y;
            sA[(kk4 + 2) * BM + m] = v.z;
            sA[(kk4 + 3) * BM + m] = v.w;
        }
        __syncthreads();

#pragma unroll
        for (int kk = 0; kk < BK; kk++) {
            float4 a4 = *(const float4*)(sA + kk * BM + lane * 4);
            const float* wrow = sW + (k0 + kk) * BN + cg * 8;
            ulonglong2 wa = *(const ulonglong2*)(wrow);
            ulonglong2 wb = *(const ulonglong2*)(wrow + 4);
            unsigned long long ar;
            ar = pack2(a4.x);
            fma2(acc[0][0], ar, wa.x); fma2(acc[0][1], ar, wa.y);
            fma2(acc[0][2], ar, wb.x); fma2(acc[0][3], ar, wb.y);
            ar = pack2(a4.y);
            fma2(acc[1][0], ar, wa.x); fma2(acc[1][1], ar, wa.y);
            fma2(acc[1][2], ar, wb.x); fma2(acc[1][3], ar, wb.y);
            ar = pack2(a4.z);
            fma2(acc[2][0], ar, wa.x); fma2(acc[2][1], ar, wa.y);
            fma2(acc[2][2], ar, wb.x); fma2(acc[2][3], ar, wb.y);
            ar = pack2(a4.w);
            fma2(acc[3][0], ar, wa.x); fma2(acc[3][1], ar, wa.y);
            fma2(acc[3][2], ar, wb.x); fma2(acc[3][3], ar, wb.y);
        }
        __syncthreads();
    }

    // ---- epilogue ----
#pragma unroll
    for (int r = 0; r < 4; r++) {
        int row = row0 + lane * 4 + r;
        if (row >= n) continue;
#pragma unroll
        for (int j = 0; j < 4; j++) {
            float lo, hi;
            unpack2(acc[r][j], lo, hi);
            int c0 = col0 + cg * 8 + 2 * j;
            if (c0 < dout) {
                float v = lo + __ldg(bias + c0);
                if (RELU) v = fmaxf(v, 0.f);
                out[(size_t)row * dout + c0] = v;
            }
            if (c0 + 1 < dout) {
                float v = hi + __ldg(bias + c0 + 1);
                if (RELU) v = fmaxf(v, 0.f);
                out[(size_t)row * dout + c0 + 1] = v;
            }
        }
    }
}

// ---------------- host launcher ----------------
extern "C" void kernel_launch(void* const* d_in, const int* in_sizes, int n_in,
                              void* d_out, int out_size) {
    const float* x    = (const float*)d_in[0];
    const int*   src0 = (const int*)d_in[1];
    const int*   dst0 = (const int*)d_in[2];
    const int*   src1 = (const int*)d_in[3];
    const int*   dst1 = (const int*)d_in[4];
    const int*   src2 = (const int*)d_in[5];
    const int*   dst2 = (const int*)d_in[6];
    const float* Ws0  = (const float*)d_in[7];
    const float* Wn0  = (const float*)d_in[8];
    const float* b0   = (const float*)d_in[9];
    const float* Ws1  = (const float*)d_in[10];
    const float* Wn1  = (const float*)d_in[11];
    const float* b1   = (const float*)d_in[12];
    const float* Ws2  = (const float*)d_in[13];
    const float* Wn2  = (const float*)d_in[14];
    const float* b2   = (const float*)d_in[15];
    float* out = (float*)d_out;

    int E0 = in_sizes[1], E1 = in_sizes[3], E2 = in_sizes[5];

    float *sum0, *deg0, *h1, *sum1, *deg1, *h2, *sum2, *deg2;
    cudaGetSymbolAddress((void**)&sum0, g_sum0);
    cudaGetSymbolAddress((void**)&deg0, g_deg0);
    cudaGetSymbolAddress((void**)&h1,   g_h1);
    cudaGetSymbolAddress((void**)&sum1, g_sum1);
    cudaGetSymbolAddress((void**)&deg1, g_deg1);
    cudaGetSymbolAddress((void**)&h2,   g_h2);
    cudaGetSymbolAddress((void**)&sum2, g_sum2);
    cudaGetSymbolAddress((void**)&deg2, g_deg2);

    const int SMEM128 = (2 * FIN * 64 + 16 * 128 + 128) * 4;  //  74240 B
    const int SMEM256 = (2 * FH  * 64 + 16 * 128 + 128) * 4;  // 139776 B
    cudaFuncSetAttribute(layer_kernel<128, true>,
                         cudaFuncAttributeMaxDynamicSharedMemorySize, SMEM128);
    cudaFuncSetAttribute(layer_kernel<256, true>,
                         cudaFuncAttributeMaxDynamicSharedMemorySize, SMEM256);
    cudaFuncSetAttribute(layer_kernel<256, false>,
                         cudaFuncAttributeMaxDynamicSharedMemorySize, SMEM256);

    // 1) zero accumulators
    zero_scratch<<<1184, 256>>>();

    // 2) layer 0: aggregate + fused dense (+ReLU) -> h1 [N1, 256]
    scatter_kernel<FIN><<<(E0 + 7) / 8, 256>>>(x, src0, dst0, E0, sum0, deg0);
    layer_kernel<FIN, true><<<dim3((N1 + 127) / 128, FH / 64), 256, SMEM128>>>(
        x, sum0, deg0, Ws0, Wn0, b0, h1, N1, FH);

    // 3) layer 1 -> h2 [N2, 256]
    scatter_kernel<FH><<<(E1 + 7) / 8, 256>>>(h1, src1, dst1, E1, sum1, deg1);
    layer_kernel<FH, true><<<dim3((N2 + 127) / 128, FH / 64), 256, SMEM256>>>(
        h1, sum1, deg1, Ws1, Wn1, b1, h2, N2, FH);

    // 4) layer 2 -> out [N3, 47]
    scatter_kernel<FH><<<(E2 + 7) / 8, 256>>>(h2, src2, dst2, E2, sum2, deg2);
    layer_kernel<FH, false><<<dim3((N3 + 127) / 128, 1), 256, SMEM256>>>(
        h2, sum2, deg2, Ws2, Wn2, b2, out, N3, FC);
}

// round 3
// speedup vs baseline: 1.5367x; 1.5367x over previous
#include <cuda_runtime.h>
#include <cstdint>

// ---------------- problem constants ----------------
#define N0 400000
#define N1 120000
#define N2 20000
#define N3 4000
#define FIN 128
#define FH  256
#define FC  47

// ---------------- device scratch ----------------
__device__ float g_sum0[(size_t)N1 * FIN];
__device__ float g_deg0[N1];
__device__ float g_h1[(size_t)N1 * FH];
__device__ float g_sum1[(size_t)N2 * FH];
__device__ float g_deg1[N2];
__device__ float g_h2[(size_t)N2 * FH];
__device__ float g_sum2[(size_t)N3 * FH];
__device__ float g_deg2[N3];

// ---------------- PTX helpers ----------------
__device__ __forceinline__ void red_add4(float* p, float4 v) {
    asm volatile("red.global.add.v4.f32 [%0], {%1,%2,%3,%4};"
                 :: "l"(p), "f"(v.x), "f"(v.y), "f"(v.z), "f"(v.w) : "memory");
}
__device__ __forceinline__ void red_add1(float* p, float v) {
    asm volatile("red.global.add.f32 [%0], %1;" :: "l"(p), "f"(v) : "memory");
}
__device__ __forceinline__ uint32_t tf32u(float x) {
    uint32_t u; asm("cvt.rna.tf32.f32 %0, %1;" : "=r"(u) : "f"(x)); return u;
}
// m16n8k8 tf32 MMA (sm_80+ baseline PTX -> tensor pipe HMMA on sm_103)
__device__ __forceinline__ void mma16n8k8(float& c0, float& c1, float& c2, float& c3,
                                          uint32_t a0, uint32_t a1, uint32_t a2, uint32_t a3,
                                          uint32_t b0, uint32_t b1) {
    asm("mma.sync.aligned.m16n8k8.row.col.f32.tf32.tf32.f32 "
        "{%0,%1,%2,%3}, {%4,%5,%6,%7}, {%8,%9}, {%0,%1,%2,%3};"
        : "+f"(c0), "+f"(c1), "+f"(c2), "+f"(c3)
        : "r"(a0), "r"(a1), "r"(a2), "r"(a3), "r"(b0), "r"(b1));
}

// ---------------- zero scratch ----------------
__global__ void zero_scratch() {
    size_t stride = (size_t)gridDim.x * blockDim.x;
    size_t i0 = (size_t)blockIdx.x * blockDim.x + threadIdx.x;
    float4 z = make_float4(0.f, 0.f, 0.f, 0.f);
    for (size_t i = i0; i < (size_t)N1 * FIN / 4; i += stride) ((float4*)g_sum0)[i] = z;
    for (size_t i = i0; i < (size_t)N2 * FH  / 4; i += stride) ((float4*)g_sum1)[i] = z;
    for (size_t i = i0; i < (size_t)N3 * FH  / 4; i += stride) ((float4*)g_sum2)[i] = z;
    for (size_t i = i0; i < N1 / 4; i += stride) ((float4*)g_deg0)[i] = z;
    for (size_t i = i0; i < N2 / 4; i += stride) ((float4*)g_deg1)[i] = z;
    for (size_t i = i0; i < N3 / 4; i += stride) ((float4*)g_deg2)[i] = z;
}

// ---------------- edge scatter: one warp per edge ----------------
template <int DIN>
__global__ void scatter_kernel(const float* __restrict__ h,
                               const int* __restrict__ src,
                               const int* __restrict__ dst, int nE,
                               float* __restrict__ sum, float* __restrict__ deg) {
    int warp = (int)((blockIdx.x * (unsigned)blockDim.x + threadIdx.x) >> 5);
    int lane = threadIdx.x & 31;
    if (warp >= nE) return;
    int s = __ldg(src + warp);
    int d = __ldg(dst + warp);
    const float4* srow = (const float4*)(h + (size_t)s * DIN);
    float* drow = sum + (size_t)d * DIN;
#pragma unroll
    for (int i = 0; i < DIN / 128; i++) {
        float4 v = __ldg(srow + lane + i * 32);
        red_add4(drow + (size_t)(lane + i * 32) * 4, v);
    }
    if (lane == 0) red_add1(deg + d, 1.0f);
}

// ---------------- SAGE layer via mma.sync tf32 ----------------
// out[n, dout] = [self | mean] @ [Ws; Wn] + bias (opt ReLU)
// CTA: BM=128 x BN=128, BK=32, 256 threads = 8 warps (warp tile 32x64).
// A staged tf32 k-minor [128][36]; B staged tf32 [32][136] ([k][n], direct from Ws/Wn).
template <int DIN, bool RELU>
__global__ void __launch_bounds__(256)
sage_mma(const float* __restrict__ hin, const float* __restrict__ nsum,
         const float* __restrict__ deg, const float* __restrict__ Ws,
         const float* __restrict__ Wn, const float* __restrict__ bias,
         float* __restrict__ out, int n, int dout) {
    constexpr int K = 2 * DIN;
    constexpr int SA_STRIDE = 36;   // 4r+tig bank pattern -> conflict-free A frags
    constexpr int SB_STRIDE = 136;  // 8k+gid bank pattern -> conflict-free B frags
    __shared__ uint32_t sA[128 * SA_STRIDE];
    __shared__ uint32_t sB[32 * SB_STRIDE];
    __shared__ float sInvD[128];

    const int tid  = threadIdx.x;
    const int lane = tid & 31, wid = tid >> 5;
    const int gid  = lane >> 2, tig = lane & 3;
    const int row0 = blockIdx.x * 128, col0 = blockIdx.y * 128;
    const int wr = wid & 3, wc = wid >> 2;          // warp tile: rows wr*32, cols wc*64
    const bool bAligned = ((dout & 3) == 0) && (col0 + 128 <= dout);

    if (tid < 128) {
        int r = row0 + tid;
        sInvD[tid] = (r < n) ? (1.0f / fmaxf(deg[r], 1.0f)) : 0.0f;
    }

    float acc[2][8][4];
#pragma unroll
    for (int mi = 0; mi < 2; mi++)
#pragma unroll
        for (int ni = 0; ni < 8; ni++)
#pragma unroll
            for (int j = 0; j < 4; j++) acc[mi][ni][j] = 0.f;

    for (int kc = 0; kc < K / 32; kc++) {
        __syncthreads();
        const int k0 = kc * 32;
        // ---- stage A tile [128 rows x 32 k] as tf32 ----
#pragma unroll
        for (int it = 0; it < 4; it++) {
            int f  = tid + it * 256;          // 0..1023 float4 slots
            int r  = f >> 3;                  // 8 float4 per row
            int c4 = (f & 7) * 4;
            int row = row0 + r;
            int k   = k0 + c4;
            float4 v = make_float4(0.f, 0.f, 0.f, 0.f);
            if (row < n) {
                if (k < DIN) {
                    v = *(const float4*)(hin + (size_t)row * DIN + k);
                } else {
                    v = *(const float4*)(nsum + (size_t)row * DIN + (k - DIN));
                    float s = sInvD[r];
                    v.x *= s; v.y *= s; v.z *= s; v.w *= s;
                }
            }
            uint4 t;
            t.x = tf32u(v.x); t.y = tf32u(v.y); t.z = tf32u(v.z); t.w = tf32u(v.w);
            *(uint4*)(sA + r * SA_STRIDE + c4) = t;
        }
        // ---- stage B tile [32 k x 128 n] as tf32 (Ws/Wn already [k][n]) ----
#pragma unroll
        for (int it = 0; it < 4; it++) {
            int f  = tid + it * 256;
            int k  = f >> 5;                  // 32 float4 per row
            int c4 = (f & 31) * 4;
            int kk = k0 + k;
            const float* Wp = (kk < DIN) ? (Ws + (size_t)kk * dout)
                                         : (Wn + (size_t)(kk - DIN) * dout);
            uint4 t;
            if (bAligned) {
                float4 v = *(const float4*)(Wp + col0 + c4);
                t.x = tf32u(v.x); t.y = tf32u(v.y); t.z = tf32u(v.z); t.w = tf32u(v.w);
            } else {
                float e[4];
#pragma unroll
                for (int j = 0; j < 4; j++) {
                    int col = col0 + c4 + j;
                    e[j] = (col < dout) ? Wp[col] : 0.f;
                }
                t.x = tf32u(e[0]); t.y = tf32u(e[1]); t.z = tf32u(e[2]); t.w = tf32u(e[3]);
            }
            *(uint4*)(sB + k * SB_STRIDE + c4) = t;
        }
        __syncthreads();

        // ---- compute: 4 k8-steps ----
#pragma unroll
        for (int ks = 0; ks < 4; ks++) {
            const int k = ks * 8;
            uint32_t a[2][4];
#pragma unroll
            for (int mi = 0; mi < 2; mi++) {
                int rb = wr * 32 + mi * 16;
                a[mi][0] = sA[(rb + gid)     * SA_STRIDE + k + tig];
                a[mi][1] = sA[(rb + gid + 8) * SA_STRIDE + k + tig];
                a[mi][2] = sA[(rb + gid)     * SA_STRIDE + k + tig + 4];
                a[mi][3] = sA[(rb + gid + 8) * SA_STRIDE + k + tig + 4];
            }
#pragma unroll
            for (int ni = 0; ni < 8; ni++) {
                int cb = wc * 64 + ni * 8 + gid;
                uint32_t b0 = sB[(k + tig)     * SB_STRIDE + cb];
                uint32_t b1 = sB[(k + tig + 4) * SB_STRIDE + cb];
#pragma unroll
                for (int mi = 0; mi < 2; mi++)
                    mma16n8k8(acc[mi][ni][0], acc[mi][ni][1], acc[mi][ni][2], acc[mi][ni][3],
                              a[mi][0], a[mi][1], a[mi][2], a[mi][3], b0, b1);
            }
        }
    }

    // ---- epilogue ----
#pragma unroll
    for (int mi = 0; mi < 2; mi++) {
        int row = row0 + wr * 32 + mi * 16 + gid;
#pragma unroll
        for (int ni = 0; ni < 8; ni++) {
            int col = col0 + wc * 64 + ni * 8 + tig * 2;
#pragma unroll
            for (int half = 0; half < 2; half++) {       // c0/c1 then c2/c3 (row+8)
                int r = row + half * 8;
                if (r >= n) continue;
                float v0 = acc[mi][ni][half * 2 + 0];
                float v1 = acc[mi][ni][half * 2 + 1];
                if (col < dout) {
                    float v = v0 + __ldg(bias + col);
                    if (RELU) v = fmaxf(v, 0.f);
                    out[(size_t)r * dout + col] = v;
                }
                if (col + 1 < dout) {
                    float v = v1 + __ldg(bias + col + 1);
                    if (RELU) v = fmaxf(v, 0.f);
                    out[(size_t)r * dout + col + 1] = v;
                }
            }
        }
    }
}

// ---------------- host launcher ----------------
extern "C" void kernel_launch(void* const* d_in, const int* in_sizes, int n_in,
                              void* d_out, int out_size) {
    const float* x    = (const float*)d_in[0];
    const int*   src0 = (const int*)d_in[1];
    const int*   dst0 = (const int*)d_in[2];
    const int*   src1 = (const int*)d_in[3];
    const int*   dst1 = (const int*)d_in[4];
    const int*   src2 = (const int*)d_in[5];
    const int*   dst2 = (const int*)d_in[6];
    const float* Ws0  = (const float*)d_in[7];
    const float* Wn0  = (const float*)d_in[8];
    const float* b0   = (const float*)d_in[9];
    const float* Ws1  = (const float*)d_in[10];
    const float* Wn1  = (const float*)d_in[11];
    const float* b1   = (const float*)d_in[12];
    const float* Ws2  = (const float*)d_in[13];
    const float* Wn2  = (const float*)d_in[14];
    const float* b2   = (const float*)d_in[15];
    float* out = (float*)d_out;

    int E0 = in_sizes[1], E1 = in_sizes[3], E2 = in_sizes[5];

    float *sum0, *deg0, *h1, *sum1, *deg1, *h2, *sum2, *deg2;
    cudaGetSymbolAddress((void**)&sum0, g_sum0);
    cudaGetSymbolAddress((void**)&deg0, g_deg0);
    cudaGetSymbolAddress((void**)&h1,   g_h1);
    cudaGetSymbolAddress((void**)&sum1, g_sum1);
    cudaGetSymbolAddress((void**)&deg1, g_deg1);
    cudaGetSymbolAddress((void**)&h2,   g_h2);
    cudaGetSymbolAddress((void**)&sum2, g_sum2);
    cudaGetSymbolAddress((void**)&deg2, g_deg2);

    zero_scratch<<<1184, 256>>>();

    // layer 0: aggregate + GEMM (+ReLU) -> h1 [N1, 256]
    scatter_kernel<FIN><<<(E0 + 7) / 8, 256>>>(x, src0, dst0, E0, sum0, deg0);
    sage_mma<FIN, true><<<dim3((N1 + 127) / 128, 2), 256>>>(
        x, sum0, deg0, Ws0, Wn0, b0, h1, N1, FH);

    // layer 1 -> h2 [N2, 256]
    scatter_kernel<FH><<<(E1 + 7) / 8, 256>>>(h1, src1, dst1, E1, sum1, deg1);
    sage_mma<FH, true><<<dim3((N2 + 127) / 128, 2), 256>>>(
        h1, sum1, deg1, Ws1, Wn1, b1, h2, N2, FH);

    // layer 2 -> out [N3, 47]
    scatter_kernel<FH><<<(E2 + 7) / 8, 256>>>(h2, src2, dst2, E2, sum2, deg2);
    sage_mma<FH, false><<<dim3((N3 + 127) / 128, 1), 256>>>(
        h2, sum2, deg2, Ws2, Wn2, b2, out, N3, FC);
}

// round 4
// speedup vs baseline: 2.1567x; 1.4035x over previous
#include <cuda_runtime.h>
#include <cstdint>

// ---------------- problem constants ----------------
#define N0 400000
#define N1 120000
#define N2 20000
#define N3 4000
#define FIN 128
#define FH  256
#define FC  47

// ---------------- device scratch ----------------
__device__ float g_sum0[(size_t)N1 * FIN];
__device__ float g_deg0[N1];
__device__ float g_h1[(size_t)N1 * FH];
__device__ float g_sum1[(size_t)N2 * FH];
__device__ float g_deg1[N2];
__device__ float g_h2[(size_t)N2 * FH];
__device__ float g_sum2[(size_t)N3 * FH];
__device__ float g_deg2[N3];

// ---------------- PTX helpers ----------------
__device__ __forceinline__ void red_add4(float* p, float4 v) {
    asm volatile("red.global.add.v4.f32 [%0], {%1,%2,%3,%4};"
                 :: "l"(p), "f"(v.x), "f"(v.y), "f"(v.z), "f"(v.w) : "memory");
}
__device__ __forceinline__ void red_add1(float* p, float v) {
    asm volatile("red.global.add.f32 [%0], %1;" :: "l"(p), "f"(v) : "memory");
}
__device__ __forceinline__ uint32_t tf32u(float x) {
    uint32_t u; asm("cvt.rna.tf32.f32 %0, %1;" : "=r"(u) : "f"(x)); return u;
}
// m16n8k8 tf32 MMA (baseline PTX -> tensor pipe on sm_103)
__device__ __forceinline__ void mma16n8k8(float& c0, float& c1, float& c2, float& c3,
                                          uint32_t a0, uint32_t a1, uint32_t a2, uint32_t a3,
                                          uint32_t b0, uint32_t b1) {
    asm("mma.sync.aligned.m16n8k8.row.col.f32.tf32.tf32.f32 "
        "{%0,%1,%2,%3}, {%4,%5,%6,%7}, {%8,%9}, {%0,%1,%2,%3};"
        : "+f"(c0), "+f"(c1), "+f"(c2), "+f"(c3)
        : "r"(a0), "r"(a1), "r"(a2), "r"(a3), "r"(b0), "r"(b1));
}

// ---------------- zero scratch ----------------
__global__ void zero_scratch() {
    size_t stride = (size_t)gridDim.x * blockDim.x;
    size_t i0 = (size_t)blockIdx.x * blockDim.x + threadIdx.x;
    float4 z = make_float4(0.f, 0.f, 0.f, 0.f);
    for (size_t i = i0; i < (size_t)N1 * FIN / 4; i += stride) ((float4*)g_sum0)[i] = z;
    for (size_t i = i0; i < (size_t)N2 * FH  / 4; i += stride) ((float4*)g_sum1)[i] = z;
    for (size_t i = i0; i < (size_t)N3 * FH  / 4; i += stride) ((float4*)g_sum2)[i] = z;
    for (size_t i = i0; i < N1 / 4; i += stride) ((float4*)g_deg0)[i] = z;
    for (size_t i = i0; i < N2 / 4; i += stride) ((float4*)g_deg1)[i] = z;
    for (size_t i = i0; i < N3 / 4; i += stride) ((float4*)g_deg2)[i] = z;
}

// ---------------- edge scatter: 4 edges per warp (MLP=4..8) ----------------
template <int DIN>
__global__ void scatter_kernel(const float* __restrict__ h,
                               const int* __restrict__ src,
                               const int* __restrict__ dst, int nE,
                               float* __restrict__ sum, float* __restrict__ deg) {
    constexpr int EPW = 4;
    constexpr int NF4 = DIN / 128;          // float4 chunks per lane per row
    int warp = (int)((blockIdx.x * (unsigned)blockDim.x + threadIdx.x) >> 5);
    int lane = threadIdx.x & 31;
    int e0 = warp * EPW;
    if (e0 >= nE) return;

    int s[EPW], d[EPW];
    bool ok[EPW];
#pragma unroll
    for (int j = 0; j < EPW; j++) {
        ok[j] = (e0 + j) < nE;
        s[j] = ok[j] ? __ldg(src + e0 + j) : 0;
        d[j] = ok[j] ? __ldg(dst + e0 + j) : 0;
    }
    // batch all gathers first (independent LDGs in flight)
    float4 v[EPW][NF4];
#pragma unroll
    for (int j = 0; j < EPW; j++)
#pragma unroll
        for (int i = 0; i < NF4; i++)
            if (ok[j])
                v[j][i] = __ldg((const float4*)(h + (size_t)s[j] * DIN) + lane + i * 32);
    // then all scatters
#pragma unroll
    for (int j = 0; j < EPW; j++)
#pragma unroll
        for (int i = 0; i < NF4; i++)
            if (ok[j])
                red_add4(sum + (size_t)d[j] * DIN + (size_t)(lane + i * 32) * 4, v[j][i]);
    if (lane == 0) {
#pragma unroll
        for (int j = 0; j < EPW; j++)
            if (ok[j]) red_add1(deg + d[j], 1.0f);
    }
}

// ---------------- SAGE layer: pipelined mma.sync tf32 GEMM ----------------
// out[n,dout] = [self | mean] @ [Ws;Wn] + bias (opt ReLU)
// BM=128 x BN=128 x BK=32, 256 thr = 8 warps (warp tile 32x64),
// double-buffered smem + register prefetch, 1 sync per k-chunk.
template <int DIN, bool RELU>
__global__ void __launch_bounds__(256)
sage_mma(const float* __restrict__ hin, const float* __restrict__ nsum,
         const float* __restrict__ deg, const float* __restrict__ Ws,
         const float* __restrict__ Wn, const float* __restrict__ bias,
         float* __restrict__ out, int n, int dout) {
    constexpr int K = 2 * DIN;
    constexpr int NCH = K / 32;
    constexpr int SA_STRIDE = 36;   // conflict-free A frag reads
    constexpr int SB_STRIDE = 136;  // conflict-free B frag reads
    constexpr int SA_ELEMS = 128 * SA_STRIDE;   // 4608
    constexpr int SB_ELEMS = 32 * SB_STRIDE;    // 4352
    extern __shared__ uint32_t smem[];
    uint32_t* sA[2] = { smem, smem + SA_ELEMS };
    uint32_t* sB[2] = { smem + 2 * SA_ELEMS, smem + 2 * SA_ELEMS + SB_ELEMS };
    float* sInvD = (float*)(smem + 2 * SA_ELEMS + 2 * SB_ELEMS);

    const int tid  = threadIdx.x;
    const int lane = tid & 31, wid = tid >> 5;
    const int gid  = lane >> 2, tig = lane & 3;
    const int row0 = blockIdx.x * 128, col0 = blockIdx.y * 128;
    const int wr = wid & 3, wc = wid >> 2;
    const bool bAligned = ((dout & 3) == 0) && (col0 + 128 <= dout);

    if (tid < 128) {
        int r = row0 + tid;
        sInvD[tid] = (r < n) ? (1.0f / fmaxf(deg[r], 1.0f)) : 0.0f;
    }
    __syncthreads();

    // per-thread staging slot coordinates (constant across chunks)
    const int ar  = (tid * 8) >> 8;               // unused placeholder avoidance
    (void)ar;

    float4 regA[4];
    float4 regB[4];

    // ---- loaders: pure global loads into registers ----
    auto loadA = [&](int kc) {
        const int k0 = kc * 32;
#pragma unroll
        for (int it = 0; it < 4; it++) {
            int f = tid + it * 256;
            int r = f >> 3, c4 = (f & 7) * 4;
            int row = row0 + r, k = k0 + c4;
            float4 v = make_float4(0.f, 0.f, 0.f, 0.f);
            if (row < n) {
                if (k < DIN) v = __ldg((const float4*)(hin + (size_t)row * DIN + k));
                else         v = __ldg((const float4*)(nsum + (size_t)row * DIN + (k - DIN)));
            }
            regA[it] = v;
        }
    };
    auto loadB = [&](int kc) {
        const int k0 = kc * 32;
#pragma unroll
        for (int it = 0; it < 4; it++) {
            int f = tid + it * 256;
            int k = f >> 5, c4 = (f & 31) * 4;
            int kk = k0 + k;
            const float* Wp = (kk < DIN) ? (Ws + (size_t)kk * dout)
                                         : (Wn + (size_t)(kk - DIN) * dout);
            if (bAligned) {
                regB[it] = __ldg((const float4*)(Wp + col0 + c4));
            } else {
                float e[4];
#pragma unroll
                for (int j = 0; j < 4; j++) {
                    int col = col0 + c4 + j;
                    e[j] = (col < dout) ? __ldg(Wp + col) : 0.f;
                }
                regB[it] = make_float4(e[0], e[1], e[2], e[3]);
            }
        }
    };
    // ---- stores: scale + tf32 round + smem ----
    auto storeA = [&](int kc, int buf) {
        const int k0 = kc * 32;
#pragma unroll
        for (int it = 0; it < 4; it++) {
            int f = tid + it * 256;
            int r = f >> 3, c4 = (f & 7) * 4;
            float4 v = regA[it];
            if (k0 + c4 >= DIN) {          // mean half: scale by inv-deg
                float s = sInvD[r];
                v.x *= s; v.y *= s; v.z *= s; v.w *= s;
            }
            uint4 t;
            t.x = tf32u(v.x); t.y = tf32u(v.y); t.z = tf32u(v.z); t.w = tf32u(v.w);
            *(uint4*)(sA[buf] + r * SA_STRIDE + c4) = t;
        }
    };
    auto storeB = [&](int buf) {
#pragma unroll
        for (int it = 0; it < 4; it++) {
            int f = tid + it * 256;
            int k = f >> 5, c4 = (f & 31) * 4;
            float4 v = regB[it];
            uint4 t;
            t.x = tf32u(v.x); t.y = tf32u(v.y); t.z = tf32u(v.z); t.w = tf32u(v.w);
            *(uint4*)(sB[buf] + k * SB_STRIDE + c4) = t;
        }
    };

    float acc[2][8][4];
#pragma unroll
    for (int mi = 0; mi < 2; mi++)
#pragma unroll
        for (int ni = 0; ni < 8; ni++)
#pragma unroll
            for (int j = 0; j < 4; j++) acc[mi][ni][j] = 0.f;

    // ---- prologue ----
    loadA(0); loadB(0);
    storeA(0, 0); storeB(0);
    __syncthreads();

    for (int kc = 0; kc < NCH; kc++) {
        const int buf = kc & 1;
        if (kc + 1 < NCH) { loadA(kc + 1); loadB(kc + 1); }   // LDGs in flight
        // ---- compute on buf ----
        const uint32_t* A = sA[buf];
        const uint32_t* B = sB[buf];
#pragma unroll
        for (int ks = 0; ks < 4; ks++) {
            const int k = ks * 8;
            uint32_t a[2][4];
#pragma unroll
            for (int mi = 0; mi < 2; mi++) {
                int rb = wr * 32 + mi * 16;
                a[mi][0] = A[(rb + gid)     * SA_STRIDE + k + tig];
                a[mi][1] = A[(rb + gid + 8) * SA_STRIDE + k + tig];
                a[mi][2] = A[(rb + gid)     * SA_STRIDE + k + tig + 4];
                a[mi][3] = A[(rb + gid + 8) * SA_STRIDE + k + tig + 4];
            }
#pragma unroll
            for (int ni = 0; ni < 8; ni++) {
                int cb = wc * 64 + ni * 8 + gid;
                uint32_t b0 = B[(k + tig)     * SB_STRIDE + cb];
                uint32_t b1 = B[(k + tig + 4) * SB_STRIDE + cb];
#pragma unroll
                for (int mi = 0; mi < 2; mi++)
                    mma16n8k8(acc[mi][ni][0], acc[mi][ni][1], acc[mi][ni][2], acc[mi][ni][3],
                              a[mi][0], a[mi][1], a[mi][2], a[mi][3], b0, b1);
            }
        }
        if (kc + 1 < NCH) { storeA(kc + 1, buf ^ 1); storeB(buf ^ 1); }
        __syncthreads();
    }

    // ---- epilogue ----
#pragma unroll
    for (int mi = 0; mi < 2; mi++) {
        int row = row0 + wr * 32 + mi * 16 + gid;
#pragma unroll
        for (int ni = 0; ni < 8; ni++) {
            int col = col0 + wc * 64 + ni * 8 + tig * 2;
#pragma unroll
            for (int half = 0; half < 2; half++) {
                int r = row + half * 8;
                if (r >= n) continue;
                float v0 = acc[mi][ni][half * 2 + 0];
                float v1 = acc[mi][ni][half * 2 + 1];
                if (col < dout) {
                    float v = v0 + __ldg(bias + col);
                    if (RELU) v = fmaxf(v, 0.f);
                    out[(size_t)r * dout + col] = v;
                }
                if (col + 1 < dout) {
                    float v = v1 + __ldg(bias + col + 1);
                    if (RELU) v = fmaxf(v, 0.f);
                    out[(size_t)r * dout + col + 1] = v;
                }
            }
        }
    }
}

// ---------------- host launcher ----------------
extern "C" void kernel_launch(void* const* d_in, const int* in_sizes, int n_in,
                              void* d_out, int out_size) {
    const float* x    = (const float*)d_in[0];
    const int*   src0 = (const int*)d_in[1];
    const int*   dst0 = (const int*)d_in[2];
    const int*   src1 = (const int*)d_in[3];
    const int*   dst1 = (const int*)d_in[4];
    const int*   src2 = (const int*)d_in[5];
    const int*   dst2 = (const int*)d_in[6];
    const float* Ws0  = (const float*)d_in[7];
    const float* Wn0  = (const float*)d_in[8];
    const float* b0   = (const float*)d_in[9];
    const float* Ws1  = (const float*)d_in[10];
    const float* Wn1  = (const float*)d_in[11];
    const float* b1   = (const float*)d_in[12];
    const float* Ws2  = (const float*)d_in[13];
    const float* Wn2  = (const float*)d_in[14];
    const float* b2   = (const float*)d_in[15];
    float* out = (float*)d_out;

    int E0 = in_sizes[1], E1 = in_sizes[3], E2 = in_sizes[5];

    float *sum0, *deg0, *h1, *sum1, *deg1, *h2, *sum2, *deg2;
    cudaGetSymbolAddress((void**)&sum0, g_sum0);
    cudaGetSymbolAddress((void**)&deg0, g_deg0);
    cudaGetSymbolAddress((void**)&h1,   g_h1);
    cudaGetSymbolAddress((void**)&sum1, g_sum1);
    cudaGetSymbolAddress((void**)&deg1, g_deg1);
    cudaGetSymbolAddress((void**)&h2,   g_h2);
    cudaGetSymbolAddress((void**)&sum2, g_sum2);
    cudaGetSymbolAddress((void**)&deg2, g_deg2);

    // dynamic smem: 2*(128*36) + 2*(32*136) + 128 floats = 72704 B
    const int SMEM = (2 * 128 * 36 + 2 * 32 * 136 + 128) * 4;
    cudaFuncSetAttribute(sage_mma<FIN, true>,
                         cudaFuncAttributeMaxDynamicSharedMemorySize, SMEM);
    cudaFuncSetAttribute(sage_mma<FH, true>,
                         cudaFuncAttributeMaxDynamicSharedMemorySize, SMEM);
    cudaFuncSetAttribute(sage_mma<FH, false>,
                         cudaFuncAttributeMaxDynamicSharedMemorySize, SMEM);

    zero_scratch<<<1184, 256>>>();

    // layer 0: aggregate + GEMM (+ReLU) -> h1 [N1, 256]
    scatter_kernel<FIN><<<(E0 + 31) / 32, 256>>>(x, src0, dst0, E0, sum0, deg0);
    sage_mma<FIN, true><<<dim3((N1 + 127) / 128, 2), 256, SMEM>>>(
        x, sum0, deg0, Ws0, Wn0, b0, h1, N1, FH);

    // layer 1 -> h2 [N2, 256]
    scatter_kernel<FH><<<(E1 + 31) / 32, 256>>>(h1, src1, dst1, E1, sum1, deg1);
    sage_mma<FH, true><<<dim3((N2 + 127) / 128, 2), 256, SMEM>>>(
        h1, sum1, deg1, Ws1, Wn1, b1, h2, N2, FH);

    // layer 2 -> out [N3, 47]
    scatter_kernel<FH><<<(E2 + 31) / 32, 256>>>(h2, src2, dst2, E2, sum2, deg2);
    sage_mma<FH, false><<<dim3((N3 + 127) / 128, 1), 256, SMEM>>>(
        h2, sum2, deg2, Ws2, Wn2, b2, out, N3, FC);
}

// round 5
// speedup vs baseline: 2.7097x; 1.2564x over previous
#include <cuda_runtime.h>
#include <cstdint>

// ---------------- problem constants ----------------
#define N1 120000
#define N2 20000
#define N3 4000
#define E0C 1800000
#define E1C 200000
#define E2C 20000
#define FIN 128
#define FH  256
#define FC  47

// ---------------- device scratch ----------------
__device__ float g_xr[(size_t)N1 * FIN];        // tf32-rounded self features, layer0
__device__ float g_mean0[(size_t)N1 * FIN];
__device__ float g_h1[(size_t)N1 * FH];
__device__ float g_mean1[(size_t)N2 * FH];
__device__ float g_h2[(size_t)N2 * FH];
__device__ float g_mean2[(size_t)N3 * FH];
__device__ float g_Wr0[256 * 256];              // [K=256][256] stacked Ws0;Wn0, tf32
__device__ float g_Wr1[512 * 256];
__device__ float g_Wr2[512 * 64];               // padded dout 47->64
// sort scratch
__device__ int g_cnt0[N1], g_cur0[N1], g_starts0[N1 + 1], g_bsum0[512];
__device__ int g_cnt1[N2], g_cur1[N2], g_starts1[N2 + 1], g_bsum1[512];
__device__ int g_cnt2[N3], g_cur2[N3], g_starts2[N3 + 1], g_bsum2[512];
__device__ int g_ssrc0[E0C], g_ssrc1[E1C], g_ssrc2[E2C];

// ---------------- helpers ----------------
__device__ __forceinline__ uint32_t tf32u(float x) {
    uint32_t u; asm("cvt.rna.tf32.f32 %0, %1;" : "=r"(u) : "f"(x)); return u;
}
__device__ __forceinline__ float tf32f(float x) { return __uint_as_float(tf32u(x)); }
__device__ __forceinline__ uint32_t smem_u32(const void* p) {
    uint32_t a;
    asm("{ .reg .u64 t; cvta.to.shared.u64 t, %1; cvt.u32.u64 %0, t; }" : "=r"(a) : "l"(p));
    return a;
}
__device__ __forceinline__ void cp_async16(uint32_t saddr, const void* g, int sz) {
    asm volatile("cp.async.cg.shared.global [%0], [%1], 16, %2;"
                 :: "r"(saddr), "l"(g), "r"(sz) : "memory");
}
__device__ __forceinline__ void cp_commit() {
    asm volatile("cp.async.commit_group;" ::: "memory");
}
template <int N>
__device__ __forceinline__ void cp_wait() {
    asm volatile("cp.async.wait_group %0;" :: "n"(N) : "memory");
}
__device__ __forceinline__ void mma16n8k8(float& c0, float& c1, float& c2, float& c3,
                                          uint32_t a0, uint32_t a1, uint32_t a2, uint32_t a3,
                                          uint32_t b0, uint32_t b1) {
    asm("mma.sync.aligned.m16n8k8.row.col.f32.tf32.tf32.f32 "
        "{%0,%1,%2,%3}, {%4,%5,%6,%7}, {%8,%9}, {%0,%1,%2,%3};"
        : "+f"(c0), "+f"(c1), "+f"(c2), "+f"(c3)
        : "r"(a0), "r"(a1), "r"(a2), "r"(a3), "r"(b0), "r"(b1));
}

// ---------------- zero counters ----------------
__global__ void zero_counters() {
    int i = blockIdx.x * blockDim.x + threadIdx.x;
    int stride = gridDim.x * blockDim.x;
    for (int j = i; j < N1; j += stride) { g_cnt0[j] = 0; g_cur0[j] = 0; }
    for (int j = i; j < N2; j += stride) { g_cnt1[j] = 0; g_cur1[j] = 0; }
    for (int j = i; j < N3; j += stride) { g_cnt2[j] = 0; g_cur2[j] = 0; }
}

// ---------------- prep: round x[:N1] + pack/round weights ----------------
__global__ void prep_kernel(const float* __restrict__ x,
                            const float* __restrict__ Ws0, const float* __restrict__ Wn0,
                            const float* __restrict__ Ws1, const float* __restrict__ Wn1,
                            const float* __restrict__ Ws2, const float* __restrict__ Wn2) {
    int i0 = blockIdx.x * blockDim.x + threadIdx.x;
    int stride = gridDim.x * blockDim.x;
    for (int i = i0; i < N1 * FIN; i += stride) g_xr[i] = tf32f(x[i]);
    for (int i = i0; i < 256 * 256; i += stride) {
        int k = i >> 8, c = i & 255;
        float v = (k < 128) ? Ws0[k * 256 + c] : Wn0[(k - 128) * 256 + c];
        g_Wr0[i] = tf32f(v);
    }
    for (int i = i0; i < 512 * 256; i += stride) {
        int k = i >> 8, c = i & 255;
        float v = (k < 256) ? Ws1[k * 256 + c] : Wn1[(k - 256) * 256 + c];
        g_Wr1[i] = tf32f(v);
    }
    for (int i = i0; i < 512 * 64; i += stride) {
        int k = i >> 6, c = i & 63;
        float v = 0.f;
        if (c < FC) v = (k < 256) ? Ws2[k * FC + c] : Wn2[(k - 256) * FC + c];
        g_Wr2[i] = tf32f(v);
    }
}

// ---------------- histogram over all 3 edge lists ----------------
__global__ void hist_all(const int* __restrict__ d0, int nE0,
                         const int* __restrict__ d1, int nE1,
                         const int* __restrict__ d2, int nE2) {
    int i = blockIdx.x * blockDim.x + threadIdx.x;
    if (i < nE0)                    atomicAdd(&g_cnt0[__ldg(d0 + i)], 1);
    else if (i < nE0 + nE1)         atomicAdd(&g_cnt1[__ldg(d1 + i - nE0)], 1);
    else if (i < nE0 + nE1 + nE2)   atomicAdd(&g_cnt2[__ldg(d2 + i - nE0 - nE1)], 1);
}

// ---------------- scan: block scan -> bsum scan -> add ----------------
__global__ void scan_block(const int* __restrict__ cnt, int n,
                           int* __restrict__ starts, int* __restrict__ bsum) {
    __shared__ int s[256];
    int i = blockIdx.x * 256 + threadIdx.x;
    int v = (i < n) ? cnt[i] : 0;
    s[threadIdx.x] = v;
    __syncthreads();
    for (int off = 1; off < 256; off <<= 1) {
        int t = (threadIdx.x >= off) ? s[threadIdx.x - off] : 0;
        __syncthreads();
        s[threadIdx.x] += t;
        __syncthreads();
    }
    if (i < n) starts[i] = s[threadIdx.x] - v;   // exclusive
    if (threadIdx.x == 255) bsum[blockIdx.x] = s[255];
}
__global__ void scan_bsum(int* __restrict__ bsum, int nb) {
    __shared__ int s[512];
    int v = (threadIdx.x < nb) ? bsum[threadIdx.x] : 0;
    s[threadIdx.x] = v;
    __syncthreads();
    for (int off = 1; off < 512; off <<= 1) {
        int t = (threadIdx.x >= off) ? s[threadIdx.x - off] : 0;
        __syncthreads();
        s[threadIdx.x] += t;
        __syncthreads();
    }
    if (threadIdx.x < nb) bsum[threadIdx.x] = s[threadIdx.x] - v;  // exclusive
}
__global__ void scan_add(int* __restrict__ starts, const int* __restrict__ bsum,
                         int n, int nE) {
    int i = blockIdx.x * 256 + threadIdx.x;
    if (i < n) starts[i] += bsum[i >> 8];
    if (blockIdx.x == 0 && threadIdx.x == 0) starts[n] = nE;
}

// ---------------- permute srcs into dst-sorted order ----------------
__global__ void permute_all(const int* __restrict__ s0, const int* __restrict__ d0, int nE0,
                            const int* __restrict__ s1, const int* __restrict__ d1, int nE1,
                            const int* __restrict__ s2, const int* __restrict__ d2, int nE2) {
    int i = blockIdx.x * blockDim.x + threadIdx.x;
    if (i < nE0) {
        int d = __ldg(d0 + i);
        g_ssrc0[g_starts0[d] + atomicAdd(&g_cur0[d], 1)] = __ldg(s0 + i);
    } else if (i < nE0 + nE1) {
        int e = i - nE0, d = __ldg(d1 + e);
        g_ssrc1[g_starts1[d] + atomicAdd(&g_cur1[d], 1)] = __ldg(s1 + e);
    } else if (i < nE0 + nE1 + nE2) {
        int e = i - nE0 - nE1, d = __ldg(d2 + e);
        g_ssrc2[g_starts2[d] + atomicAdd(&g_cur2[d], 1)] = __ldg(s2 + e);
    }
}

// ---------------- segmented mean aggregation: one warp per dst node ----------------
template <int DIN>
__global__ void agg_kernel(const float* __restrict__ h, const int* __restrict__ ssrc,
                           const int* __restrict__ starts, int nD,
                           float* __restrict__ mean) {
    constexpr int NF4 = DIN / 128;
    int w = (int)((blockIdx.x * (unsigned)blockDim.x + threadIdx.x) >> 5);
    int lane = threadIdx.x & 31;
    if (w >= nD) return;
    int beg = __ldg(starts + w), end = __ldg(starts + w + 1);
    float4 acc[NF4];
#pragma unroll
    for (int j = 0; j < NF4; j++) acc[j] = make_float4(0.f, 0.f, 0.f, 0.f);
    int i = beg;
    for (; i + 2 <= end; i += 2) {
        int s0 = __ldg(ssrc + i), s1 = __ldg(ssrc + i + 1);
        float4 a[NF4], b[NF4];
#pragma unroll
        for (int j = 0; j < NF4; j++)
            a[j] = __ldg((const float4*)(h + (size_t)s0 * DIN) + lane + j * 32);
#pragma unroll
        for (int j = 0; j < NF4; j++)
            b[j] = __ldg((const float4*)(h + (size_t)s1 * DIN) + lane + j * 32);
#pragma unroll
        for (int j = 0; j < NF4; j++) {
            acc[j].x += a[j].x + b[j].x; acc[j].y += a[j].y + b[j].y;
            acc[j].z += a[j].z + b[j].z; acc[j].w += a[j].w + b[j].w;
        }
    }
    if (i < end) {
        int s0 = __ldg(ssrc + i);
#pragma unroll
        for (int j = 0; j < NF4; j++) {
            float4 a = __ldg((const float4*)(h + (size_t)s0 * DIN) + lane + j * 32);
            acc[j].x += a.x; acc[j].y += a.y; acc[j].z += a.z; acc[j].w += a.w;
        }
    }
    float inv = (end > beg) ? (1.0f / (float)(end - beg)) : 0.0f;
#pragma unroll
    for (int j = 0; j < NF4; j++) {
        float4 o;
        o.x = tf32f(acc[j].x * inv); o.y = tf32f(acc[j].y * inv);
        o.z = tf32f(acc[j].z * inv); o.w = tf32f(acc[j].w * inv);
        *((float4*)(mean + (size_t)w * DIN) + lane + j * 32) = o;
    }
}

// ---------------- GEMM: cp.async double-buffered mma.sync tf32 ----------------
// out[n,dout] = [self | mean] @ Wr + bias; operands pre-rounded to tf32.
// BM=128 x BN=128 x BK=32, 256 thr = 8 warps (warp tile 32x64).
template <int K, int DOUTP, bool RELU, bool ROUND_OUT>
__global__ void __launch_bounds__(256, 2)
sage_gemm(const float* __restrict__ selfp, const float* __restrict__ meanp,
          const float* __restrict__ Wr, const float* __restrict__ bias,
          float* __restrict__ out, int n, int dout) {
    constexpr int DIN = K / 2;
    constexpr int NCH = K / 32;
    constexpr int SA_STRIDE = 36;   // floats; 144B rows (16B multiple)
    constexpr int SB_STRIDE = 136;  // floats; 544B rows
    constexpr int SA_ELEMS = 128 * SA_STRIDE;
    constexpr int SB_ELEMS = 32 * SB_STRIDE;
    extern __shared__ uint32_t smem[];
    uint32_t* sA[2] = { smem, smem + SA_ELEMS };
    uint32_t* sB[2] = { smem + 2 * SA_ELEMS, smem + 2 * SA_ELEMS + SB_ELEMS };
    const uint32_t sA32[2] = { smem_u32(sA[0]), smem_u32(sA[1]) };
    const uint32_t sB32[2] = { smem_u32(sB[0]), smem_u32(sB[1]) };

    const int tid  = threadIdx.x;
    const int lane = tid & 31, wid = tid >> 5;
    const int gid  = lane >> 2, tig = lane & 3;
    const int row0 = blockIdx.x * 128, col0 = blockIdx.y * 128;
    const int wr = wid & 3, wc = wid >> 2;

    auto issue = [&](int kc, int buf) {
        const int k0 = kc * 32;
        const float* base = (k0 < DIN) ? selfp : meanp;
        const int kk0 = (k0 < DIN) ? k0 : (k0 - DIN);
        // A tile [128 x 32]
#pragma unroll
        for (int it = 0; it < 4; it++) {
            int f = tid + it * 256;
            int r = f >> 3, c4 = (f & 7) * 4;
            bool ok = (row0 + r) < n;
            const float* g = base + (ok ? ((size_t)(row0 + r) * DIN + kk0 + c4) : 0);
            cp_async16(sA32[buf] + (uint32_t)(r * SA_STRIDE + c4) * 4u, g, ok ? 16 : 0);
        }
        // B tile [32 x 128]
#pragma unroll
        for (int it = 0; it < 4; it++) {
            int f = tid + it * 256;
            int k = f >> 5, c4 = (f & 31) * 4;
            bool ok = (col0 + c4) < DOUTP;
            const float* g = Wr + (ok ? ((size_t)(k0 + k) * DOUTP + col0 + c4) : 0);
            cp_async16(sB32[buf] + (uint32_t)(k * SB_STRIDE + c4) * 4u, g, ok ? 16 : 0);
        }
        cp_commit();
    };

    float acc[2][8][4];
#pragma unroll
    for (int mi = 0; mi < 2; mi++)
#pragma unroll
        for (int ni = 0; ni < 8; ni++)
#pragma unroll
            for (int j = 0; j < 4; j++) acc[mi][ni][j] = 0.f;

    issue(0, 0);
    for (int kc = 0; kc < NCH; kc++) {
        const int buf = kc & 1;
        if (kc + 1 < NCH) { issue(kc + 1, buf ^ 1); cp_wait<1>(); }
        else              { cp_wait<0>(); }
        __syncthreads();
        const uint32_t* A = sA[buf];
        const uint32_t* B = sB[buf];
#pragma unroll
        for (int ks = 0; ks < 4; ks++) {
            const int k = ks * 8;
            uint32_t a[2][4];
#pragma unroll
            for (int mi = 0; mi < 2; mi++) {
                int rb = wr * 32 + mi * 16;
                a[mi][0] = A[(rb + gid)     * SA_STRIDE + k + tig];
                a[mi][1] = A[(rb + gid + 8) * SA_STRIDE + k + tig];
                a[mi][2] = A[(rb + gid)     * SA_STRIDE + k + tig + 4];
                a[mi][3] = A[(rb + gid + 8) * SA_STRIDE + k + tig + 4];
            }
#pragma unroll
            for (int ni = 0; ni < 8; ni++) {
                int cb = wc * 64 + ni * 8 + gid;
                uint32_t b0 = B[(k + tig)     * SB_STRIDE + cb];
                uint32_t b1 = B[(k + tig + 4) * SB_STRIDE + cb];
#pragma unroll
                for (int mi = 0; mi < 2; mi++)
                    mma16n8k8(acc[mi][ni][0], acc[mi][ni][1], acc[mi][ni][2], acc[mi][ni][3],
                              a[mi][0], a[mi][1], a[mi][2], a[mi][3], b0, b1);
            }
        }
        __syncthreads();   // buf free before it is re-filled at kc+2
    }

    // ---- epilogue ----
#pragma unroll
    for (int mi = 0; mi < 2; mi++) {
        int row = row0 + wr * 32 + mi * 16 + gid;
#pragma unroll
        for (int ni = 0; ni < 8; ni++) {
            int col = col0 + wc * 64 + ni * 8 + tig * 2;
#pragma unroll
            for (int half = 0; half < 2; half++) {
                int r = row + half * 8;
                if (r >= n) continue;
#pragma unroll
                for (int q = 0; q < 2; q++) {
                    int c = col + q;
                    if (c >= dout) continue;
                    float v = acc[mi][ni][half * 2 + q] + __ldg(bias + c);
                    if (RELU) v = fmaxf(v, 0.f);
                    if (ROUND_OUT) v = tf32f(v);
                    out[(size_t)r * dout + c] = v;
                }
            }
        }
    }
}

// ---------------- host launcher ----------------
extern "C" void kernel_launch(void* const* d_in, const int* in_sizes, int n_in,
                              void* d_out, int out_size) {
    const float* x    = (const float*)d_in[0];
    const int*   src0 = (const int*)d_in[1];
    const int*   dst0 = (const int*)d_in[2];
    const int*   src1 = (const int*)d_in[3];
    const int*   dst1 = (const int*)d_in[4];
    const int*   src2 = (const int*)d_in[5];
    const int*   dst2 = (const int*)d_in[6];
    const float* Ws0  = (const float*)d_in[7];
    const float* Wn0  = (const float*)d_in[8];
    const float* b0   = (const float*)d_in[9];
    const float* Ws1  = (const float*)d_in[10];
    const float* Wn1  = (const float*)d_in[11];
    const float* b1   = (const float*)d_in[12];
    const float* Ws2  = (const float*)d_in[13];
    const float* Wn2  = (const float*)d_in[14];
    const float* b2   = (const float*)d_in[15];
    float* out = (float*)d_out;

    int E0 = in_sizes[1], E1 = in_sizes[3], E2 = in_sizes[5];
    int ET = E0 + E1 + E2;

    float *xr, *mean0, *h1, *mean1, *h2, *mean2, *Wr0, *Wr1, *Wr2;
    int *cnt0, *cnt1, *cnt2, *st0, *st1, *st2, *bs0, *bs1, *bs2, *ss0, *ss1, *ss2;
    cudaGetSymbolAddress((void**)&xr, g_xr);
    cudaGetSymbolAddress((void**)&mean0, g_mean0);
    cudaGetSymbolAddress((void**)&h1, g_h1);
    cudaGetSymbolAddress((void**)&mean1, g_mean1);
    cudaGetSymbolAddress((void**)&h2, g_h2);
    cudaGetSymbolAddress((void**)&mean2, g_mean2);
    cudaGetSymbolAddress((void**)&Wr0, g_Wr0);
    cudaGetSymbolAddress((void**)&Wr1, g_Wr1);
    cudaGetSymbolAddress((void**)&Wr2, g_Wr2);
    cudaGetSymbolAddress((void**)&cnt0, g_cnt0);
    cudaGetSymbolAddress((void**)&cnt1, g_cnt1);
    cudaGetSymbolAddress((void**)&cnt2, g_cnt2);
    cudaGetSymbolAddress((void**)&st0, g_starts0);
    cudaGetSymbolAddress((void**)&st1, g_starts1);
    cudaGetSymbolAddress((void**)&st2, g_starts2);
    cudaGetSymbolAddress((void**)&bs0, g_bsum0);
    cudaGetSymbolAddress((void**)&bs1, g_bsum1);
    cudaGetSymbolAddress((void**)&bs2, g_bsum2);
    cudaGetSymbolAddress((void**)&ss0, g_ssrc0);
    cudaGetSymbolAddress((void**)&ss1, g_ssrc1);
    cudaGetSymbolAddress((void**)&ss2, g_ssrc2);

    const int SMEM = (2 * 128 * 36 + 2 * 32 * 136) * 4;  // 71680 B
    cudaFuncSetAttribute(sage_gemm<256, 256, true, true>,
                         cudaFuncAttributeMaxDynamicSharedMemorySize, SMEM);
    cudaFuncSetAttribute(sage_gemm<512, 256, true, true>,
                         cudaFuncAttributeMaxDynamicSharedMemorySize, SMEM);
    cudaFuncSetAttribute(sage_gemm<512, 64, false, false>,
                         cudaFuncAttributeMaxDynamicSharedMemorySize, SMEM);

    // ---- sort pipeline (inputs only) ----
    zero_counters<<<160, 256>>>();
    prep_kernel<<<1184, 256>>>(x, Ws0, Wn0, Ws1, Wn1, Ws2, Wn2);
    hist_all<<<(ET + 255) / 256, 256>>>(dst0, E0, dst1, E1, dst2, E2);
    int nb0 = (N1 + 255) / 256, nb1 = (N2 + 255) / 256, nb2 = (N3 + 255) / 256;
    scan_block<<<nb0, 256>>>(cnt0, N1, st0, bs0);
    scan_block<<<nb1, 256>>>(cnt1, N2, st1, bs1);
    scan_block<<<nb2, 256>>>(cnt2, N3, st2, bs2);
    scan_bsum<<<1, 512>>>(bs0, nb0);
    scan_bsum<<<1, 512>>>(bs1, nb1);
    scan_bsum<<<1, 512>>>(bs2, nb2);
    scan_add<<<nb0, 256>>>(st0, bs0, N1, E0);
    scan_add<<<nb1, 256>>>(st1, bs1, N2, E1);
    scan_add<<<nb2, 256>>>(st2, bs2, N3, E2);
    permute_all<<<(ET + 255) / 256, 256>>>(src0, dst0, E0, src1, dst1, E1, src2, dst2, E2);

    // ---- layer 0 ----
    agg_kernel<FIN><<<(N1 * 32 + 255) / 256, 256>>>(x, ss0, st0, N1, mean0);
    sage_gemm<256, 256, true, true><<<dim3((N1 + 127) / 128, 2), 256, SMEM>>>(
        xr, mean0, Wr0, b0, h1, N1, FH);

    // ---- layer 1 ----
    agg_kernel<FH><<<(N2 * 32 + 255) / 256, 256>>>(h1, ss1, st1, N2, mean1);
    sage_gemm<512, 256, true, true><<<dim3((N2 + 127) / 128, 2), 256, SMEM>>>(
        h1, mean1, Wr1, b1, h2, N2, FH);

    // ---- layer 2 ----
    agg_kernel<FH><<<(N3 * 32 + 255) / 256, 256>>>(h2, ss2, st2, N3, mean2);
    sage_gemm<512, 64, false, false><<<dim3((N3 + 127) / 128, 1), 256, SMEM>>>(
        h2, mean2, Wr2, b2, out, N3, FC);
}